// round 16
// baseline (speedup 1.0000x reference)
#include <cuda_runtime.h>
#include <cstdint>

// Problem dims (fixed by reference)
#define BSZ  8
#define SDIM 2048
#define IDIM 1024
#define HDIM 4096
#define ODIM 1024
#define MDIM (BSZ * SDIM)   // 16384

// Scratch (no cudaMalloc allowed)
__device__ float g_decay[(size_t)MDIM * IDIM];     // 64 MB
__device__ float g_combined[(size_t)MDIM * IDIM];  // 64 MB (tf32-rounded)
__device__ float g_hidden[(size_t)MDIM * HDIM];    // 256 MB (tf32-rounded)
__device__ float g_xr[(size_t)MDIM * IDIM];        // 64 MB (tf32-rounded x)
__device__ float g_wgr[(size_t)IDIM * IDIM];       // 4 MB
__device__ float g_w1r[(size_t)HDIM * IDIM];       // 16 MB
__device__ float g_w2r[(size_t)ODIM * HDIM];       // 16 MB

// tcgen05 only exists in the arch-specific (sm_103a) compilation pass.
#if !defined(__CUDA_ARCH__) || defined(__CUDA_ARCH_FEAT_SM103_ALL) || \
    defined(__CUDA_ARCH_FEAT_SM100_ALL) || defined(__CUDA_ARCH_SPECIFIC__)
#define KUSE_TC 1
#else
#define KUSE_TC 0
#endif

// ---------------------------------------------------------------------------
// Common helpers
// ---------------------------------------------------------------------------
__device__ __forceinline__ uint32_t smem_u32(const void* p) {
    return (uint32_t)__cvta_generic_to_shared(p);
}
__device__ __forceinline__ float to_tf32(float x) {
    float r;
    asm("cvt.rna.tf32.f32 %0, %1;" : "=f"(r) : "f"(x));
    return r;
}
__device__ __forceinline__ void cp16(uint32_t s, const void* g) {
    asm volatile("cp.async.cg.shared.global [%0], [%1], 16;" ::"r"(s), "l"(g));
}

#if KUSE_TC
__device__ __forceinline__ void mbar_init(uint32_t a, uint32_t cnt) {
    asm volatile("mbarrier.init.shared.b64 [%0], %1;" ::"r"(a), "r"(cnt)
                 : "memory");
}
__device__ __forceinline__ void mbar_wait(uint32_t a, uint32_t parity) {
    asm volatile(
        "{\n\t.reg .pred P;\n"
        "W%=:\n\t"
        "mbarrier.try_wait.parity.acquire.cta.shared::cta.b64 P, [%0], %1, 0x989680;\n\t"
        "@P bra D%=;\n\t"
        "bra W%=;\n"
        "D%=:\n\t}"
        ::"r"(a), "r"(parity)
        : "memory");
}
__device__ __forceinline__ void mma_tf32(uint32_t d, uint64_t ad, uint64_t bd,
                                         uint32_t idesc, bool acc) {
    uint32_t en = acc ? 1u : 0u;
    asm volatile(
        "{\n\t.reg .pred p;\n\t"
        "setp.ne.u32 p, %4, 0;\n\t"
        "tcgen05.mma.cta_group::1.kind::tf32 [%0], %1, %2, %3, {%5,%5,%5,%5}, p;\n\t}"
        ::"r"(d), "l"(ad), "l"(bd), "r"(idesc), "r"(en), "r"(0u)
        : "memory");
}
#define LDTM_X32(r, a)                                                       \
    asm volatile(                                                            \
        "tcgen05.ld.sync.aligned.32x32b.x32.b32 "                            \
        "{%0,%1,%2,%3,%4,%5,%6,%7,%8,%9,%10,%11,%12,%13,%14,%15,"            \
        "%16,%17,%18,%19,%20,%21,%22,%23,%24,%25,%26,%27,%28,%29,%30,%31}, " \
        "[%32];"                                                             \
        : "=r"((r)[0]), "=r"((r)[1]), "=r"((r)[2]), "=r"((r)[3]),            \
          "=r"((r)[4]), "=r"((r)[5]), "=r"((r)[6]), "=r"((r)[7]),            \
          "=r"((r)[8]), "=r"((r)[9]), "=r"((r)[10]), "=r"((r)[11]),          \
          "=r"((r)[12]), "=r"((r)[13]), "=r"((r)[14]), "=r"((r)[15]),        \
          "=r"((r)[16]), "=r"((r)[17]), "=r"((r)[18]), "=r"((r)[19]),        \
          "=r"((r)[20]), "=r"((r)[21]), "=r"((r)[22]), "=r"((r)[23]),        \
          "=r"((r)[24]), "=r"((r)[25]), "=r"((r)[26]), "=r"((r)[27]),        \
          "=r"((r)[28]), "=r"((r)[29]), "=r"((r)[30]), "=r"((r)[31])         \
        : "r"(a))
#endif  // KUSE_TC

// ---------------------------------------------------------------------------
// GEMM: C[m,n] = act(sum_k A[m,k]*B[n,k] + bias[n])
// A [M,K] row-major, B [N,K] row-major, both tf32-rounded, normal layout.
// PERSISTENT: grid of 128 CTAs; each CTA loops over its (bm,bn) tiles with a
// flattened (tile, kt) step stream. Loads lead MMA by 2 steps ACROSS tile
// boundaries, so the 3-stage pipeline never drains; tmem alloc once per CTA.
// Per tile: 256x256 via two M=128/N=256 MMA dispatches (TMEM cols 0 / 256).
// ---------------------------------------------------------------------------
#define BM 256
#define BN 256
#define TB_A 32768             // two A tiles: 2 x (128 rows x 128 B)
#define TB_B 32768             // B tile: 256 rows x 128 B
#define TB_ST (TB_A + TB_B)    // 64 KB
#define STAGES 3
#define GRIDP 128              // persistent grid (divides 256/1024/256 tiles)
#define SMEM_REQ (STAGES * TB_ST + 1024 + 64)

static constexpr uint64_t DESC_BASE =
    (2ull << 61) | (1ull << 46) | (64ull << 32) | (1ull << 16);  // SW128 K-major
// idesc: dtype F32, a/btype TF32(2), N=256 (per dispatch), M=128
#define IDESC ((1u << 4) | (2u << 7) | (2u << 10) | (32u << 17) | (8u << 24))

enum { EP_SIG = 0, EP_RELU = 1, EP_BIAS = 2 };

template <int EP, bool ROUND>
__global__ void __launch_bounds__(256, 1)
gemm_tc(const float* __restrict__ A, const float* __restrict__ B,
        float* __restrict__ C, const float* __restrict__ bias, int M, int N,
        int K) {
    extern __shared__ char dsm[];
    const int tid  = threadIdx.x;
    const int warp = tid >> 5;
    const int lane = tid & 31;
    const int nbn    = N / BN;             // tiles along N
    const int ntiles = (M / BM) * nbn;
    const int nk     = K >> 5;             // k-steps per tile

#if KUSE_TC
    const uint32_t sb    = smem_u32(dsm);
    const uint32_t tiles = (sb + 1023u) & ~1023u;
    const uint32_t ctrl  = tiles + STAGES * TB_ST;
    const uint32_t DONEB = ctrl;              // 3 x 8B mbars
    const uint32_t TPTR  = ctrl + 32;

    if (tid == 0) {
#pragma unroll
        for (int s = 0; s < STAGES; s++) mbar_init(DONEB + 8 * s, 1);
    }
    if (warp == 0) {
        asm volatile(
            "tcgen05.alloc.cta_group::1.sync.aligned.shared::cta.b32 [%0], %1;"
            ::"r"(TPTR), "r"(512u)
            : "memory");
        asm volatile("tcgen05.relinquish_alloc_permit.cta_group::1.sync.aligned;");
    }
    __syncthreads();
    uint32_t tmem;
    asm volatile("ld.shared.b32 %0, [%1];" : "=r"(tmem) : "r"(TPTR));

    const int cnt   = (ntiles - (int)blockIdx.x + (int)gridDim.x - 1) /
                      (int)gridDim.x;        // my tile count
    const int total = cnt * nk;              // my flattened steps

    auto tile_org = [&](int j, int& tbm, int& tbn) {
        const int t = (int)blockIdx.x + j * (int)gridDim.x;
        tbm = (t / nbn) * BM;
        tbn = (t % nbn) * BN;
    };

    auto load_tile = [&](int st, int tbm, int tbn, int kt) {
        const uint32_t As = tiles + st * TB_ST;   // A0 | A1 (16KB each)
        const uint32_t Bs = As + TB_A;
        const float* Ag = A + (size_t)tbm * K + kt * 32;
        const float* Bg = B + (size_t)tbn * K + kt * 32;
#pragma unroll
        for (int t = 0; t < 8; t++) {             // A: 8 chunks/thread
            const int ch = tid + t * 256;
            const int r  = ch >> 3;               // 0..255
            const int c  = ch & 7;
            uint32_t off = (uint32_t)((r & 127) * 128 + c * 16);
            off ^= (off >> 3) & 0x70;             // SW128 swizzle
            cp16(As + (uint32_t)(r >> 7) * 16384u + off,
                 Ag + (size_t)r * K + c * 4);
        }
#pragma unroll
        for (int t = 0; t < 8; t++) {             // B: 8 chunks/thread
            const int ch = tid + t * 256;
            const int r  = ch >> 3;
            const int c  = ch & 7;
            uint32_t off = (uint32_t)(r * 128 + c * 16);
            off ^= (off >> 3) & 0x70;
            cp16(Bs + off, Bg + (size_t)r * K + c * 4);
        }
        asm volatile("cp.async.commit_group;");
    };

    auto load_step = [&](int S) {
        const int j  = S / nk;
        const int kt = S - j * nk;
        int tbm, tbn;
        tile_org(j, tbm, tbn);
        load_tile(S % STAGES, tbm, tbn, kt);
    };

    if (total > 0) load_step(0);
    if (total > 1) load_step(1);

    int S = 0;
    for (int j = 0; j < cnt; j++) {
        int tbm, tbn;
        tile_org(j, tbm, tbn);
        for (int kt = 0; kt < nk; kt++, S++) {
            if (S == total - 1)
                asm volatile("cp.async.wait_group 0;");
            else
                asm volatile("cp.async.wait_group 1;");  // step S resident
            __syncthreads();
            asm volatile("fence.proxy.async.shared::cta;" ::: "memory");
            if (tid == 0) {
                const uint32_t As = tiles + (S % STAGES) * TB_ST;
                const uint64_t ad0 =
                    DESC_BASE | ((uint64_t)(As >> 4) & 0x3FFF);
                const uint64_t ad1 =
                    DESC_BASE | ((uint64_t)((As + 16384) >> 4) & 0x3FFF);
                const uint64_t bd =
                    DESC_BASE | ((uint64_t)((As + TB_A) >> 4) & 0x3FFF);
#pragma unroll
                for (int s = 0; s < 4; s++) {  // 4 x K=8 steps (+32B each)
                    const bool acc = (kt > 0) || (s > 0);
                    mma_tf32(tmem, ad0 + 2 * s, bd + 2 * s, IDESC, acc);
                    mma_tf32(tmem + 256, ad1 + 2 * s, bd + 2 * s, IDESC, acc);
                }
                asm volatile(
                    "tcgen05.commit.cta_group::1.mbarrier::arrive::one.shared::cluster.b64 [%0];"
                    ::"r"(DONEB + 8 * (S % STAGES))
                    : "memory");
            }
            const int tl = S + 2;
            if (tl < total) {
                if (tl >= STAGES)  // buffer last read by MMA of step tl-3
                    mbar_wait(DONEB + 8 * (tl % STAGES),
                              (uint32_t)(((tl / STAGES) - 1) & 1));
                load_step(tl);
            }
            __syncthreads();

            if (kt == nk - 1) {
                // ---- inline per-tile epilogue (loads already 2 ahead) ----
                mbar_wait(DONEB + 8 * (S % STAGES),
                          (uint32_t)((S / STAGES) & 1));
                asm volatile("tcgen05.fence::after_thread_sync;" ::: "memory");

                const int mt = warp >> 2;  // M-tile
                const int wq = warp & 3;   // lane partition (rows)
                const uint32_t tpart = tmem + ((uint32_t)wq << 21);
                const int row = tbm + mt * 128 + wq * 32 + lane;
#pragma unroll
                for (int h = 0; h < 8; h++) {
                    const int tcol = mt * 256 + h * 32;
                    const int ncol = h * 32;
                    uint32_t r[32];
                    LDTM_X32(r, tpart + tcol);
                    asm volatile("tcgen05.wait::ld.sync.aligned;" ::: "memory");
                    float v[32];
#pragma unroll
                    for (int jj = 0; jj < 32; jj++) {
                        float t = __uint_as_float(r[jj]) +
                                  __ldg(&bias[tbn + ncol + jj]);
                        if (EP == EP_RELU) t = fmaxf(t, 0.0f);
                        if (EP == EP_SIG) t = 1.0f / (1.0f + __expf(-t));
                        if (ROUND) t = to_tf32(t);
                        v[jj] = t;
                    }
                    float* dst = &C[(size_t)row * N + tbn + ncol];
#pragma unroll
                    for (int q = 0; q < 8; q++)
                        *(float4*)&dst[q * 4] =
                            make_float4(v[q * 4], v[q * 4 + 1], v[q * 4 + 2],
                                        v[q * 4 + 3]);
                }
                asm volatile("tcgen05.fence::before_thread_sync;" ::: "memory");
                // next iteration's __syncthreads orders LDTM completion
                // before tid0 overwrites TMEM (acc=false restart).
            }
        }
    }

    __syncthreads();
    if (warp == 0)
        asm volatile("tcgen05.dealloc.cta_group::1.sync.aligned.b32 %0, %1;"
                     ::"r"(tmem), "r"(512u));

#else
    // ============ naive fallback (plain sm_103 pass; never runs) ==========
    for (int t = blockIdx.x; t < ntiles; t += gridDim.x) {
        const int tbm = (t / nbn) * BM;
        const int tbn = (t % nbn) * BN;
        for (int e = tid; e < BM * BN; e += 256) {
            const int r  = e / BN;
            const int cc = e % BN;
            float acc = 0.0f;
            for (int k = 0; k < K; k++)
                acc += A[(size_t)(tbm + r) * K + k] *
                       B[(size_t)(tbn + cc) * K + k];
            float tv = acc + bias[tbn + cc];
            if (EP == EP_RELU) tv = fmaxf(tv, 0.0f);
            if (EP == EP_SIG) tv = 1.0f / (1.0f + __expf(-tv));
            if (ROUND) tv = to_tf32(tv);
            C[(size_t)(tbm + r) * N + tbn + cc] = tv;
        }
    }
#endif  // KUSE_TC
}

// ---------------------------------------------------------------------------
// Round-to-nearest tf32 prep
// ---------------------------------------------------------------------------
__global__ void round_kernel(const float* __restrict__ in,
                             float* __restrict__ out, size_t n) {
    for (size_t i = (size_t)blockIdx.x * blockDim.x + threadIdx.x; i < n;
         i += (size_t)gridDim.x * blockDim.x)
        out[i] = to_tf32(in[i]);
}

// ---------------------------------------------------------------------------
// Sequential buffer scan; combined is tf32-rounded (GEMM A input).
// ---------------------------------------------------------------------------
__global__ void scan_kernel(const float* __restrict__ x,
                            const float* __restrict__ decay,
                            float* __restrict__ combined) {
    const int i = blockIdx.x * blockDim.x + threadIdx.x;
    const int b = blockIdx.y;
    const size_t base = (size_t)b * SDIM * IDIM + i;

    float buf = 0.0f;
    for (int t0 = 0; t0 < SDIM; t0 += 8) {
        float d[8], xv[8];
#pragma unroll
        for (int j = 0; j < 8; j++) {
            const size_t idx = base + (size_t)(t0 + j) * IDIM;
            d[j]  = decay[idx];
            xv[j] = x[idx];
        }
#pragma unroll
        for (int j = 0; j < 8; j++) {
            buf = buf * d[j] + (1.0f - d[j]) * xv[j];
            combined[base + (size_t)(t0 + j) * IDIM] = to_tf32(xv[j] * d[j] + buf);
        }
    }
}

// ---------------------------------------------------------------------------
// Launch
// ---------------------------------------------------------------------------
extern "C" void kernel_launch(void* const* d_in, const int* in_sizes, int n_in,
                              void* d_out, int out_size) {
    (void)in_sizes; (void)n_in; (void)out_size;
    const float* x  = (const float*)d_in[0];
    const float* W1 = (const float*)d_in[1];
    const float* b1 = (const float*)d_in[2];
    const float* W2 = (const float*)d_in[3];
    const float* b2 = (const float*)d_in[4];
    const float* Wg = (const float*)d_in[5];
    const float* bg = (const float*)d_in[6];
    float* out = (float*)d_out;

    void *pd, *pc, *ph, *pxr, *pwg, *pw1, *pw2;
    cudaGetSymbolAddress(&pd, g_decay);
    cudaGetSymbolAddress(&pc, g_combined);
    cudaGetSymbolAddress(&ph, g_hidden);
    cudaGetSymbolAddress(&pxr, g_xr);
    cudaGetSymbolAddress(&pwg, g_wgr);
    cudaGetSymbolAddress(&pw1, g_w1r);
    cudaGetSymbolAddress(&pw2, g_w2r);
    float* decay    = (float*)pd;
    float* combined = (float*)pc;
    float* hidden   = (float*)ph;
    float* xr       = (float*)pxr;
    float* wgr      = (float*)pwg;
    float* w1r      = (float*)pw1;
    float* w2r      = (float*)pw2;

    cudaFuncSetAttribute(gemm_tc<EP_SIG, false>,
                         cudaFuncAttributeMaxDynamicSharedMemorySize, SMEM_REQ);
    cudaFuncSetAttribute(gemm_tc<EP_RELU, true>,
                         cudaFuncAttributeMaxDynamicSharedMemorySize, SMEM_REQ);
    cudaFuncSetAttribute(gemm_tc<EP_BIAS, false>,
                         cudaFuncAttributeMaxDynamicSharedMemorySize, SMEM_REQ);

    // tf32 round-to-nearest prep (weights + x)
    round_kernel<<<1024, 256>>>(x, xr, (size_t)MDIM * IDIM);
    round_kernel<<<256, 256>>>(Wg, wgr, (size_t)IDIM * IDIM);
    round_kernel<<<512, 256>>>(W1, w1r, (size_t)HDIM * IDIM);
    round_kernel<<<512, 256>>>(W2, w2r, (size_t)ODIM * HDIM);

    // 1) decay = sigmoid(x @ Wg^T + bg)     [256 tiles over 128 CTAs]
    gemm_tc<EP_SIG, false><<<GRIDP, 256, SMEM_REQ>>>(xr, wgr, decay, bg, MDIM,
                                                     IDIM, IDIM);
    // 2) recurrence -> combined (tf32-rounded)
    scan_kernel<<<dim3(IDIM / 64, BSZ), 64>>>(x, decay, combined);
    // 3) hidden = relu(combined @ W1^T + b1), tf32-rounded [1024 tiles]
    gemm_tc<EP_RELU, true><<<GRIDP, 256, SMEM_REQ>>>(combined, w1r, hidden, b1,
                                                     MDIM, HDIM, IDIM);
    // 4) out = hidden @ W2^T + b2           [256 tiles]
    gemm_tc<EP_BIAS, false><<<GRIDP, 256, SMEM_REQ>>>(hidden, w2r, out, b2,
                                                      MDIM, ODIM, HDIM);
}